// round 1
// baseline (speedup 1.0000x reference)
#include <cuda_runtime.h>
#include <math.h>

#define NUM_B   4
#define SEQ_T   4096
#define NTOK    (NUM_B*SEQ_T)      // 16384
#define MODEL   2048
#define RANK    16
#define DD      1024               // NUM_HEADS * PE_DIM
#define QK_ELEMS 33554432          // NTOK*16*128

// scratch (allocation-free rule: __device__ globals)
__device__ float g_u[NTOK*RANK];   // x_norm @ W1
__device__ float g_U[NTOK*RANK];   // cumsum over t of g_u

// ---------------------------------------------------------------------------
// Kernel A: per-head L2 normalize + GEMM with W1 (2048x16) -> u (NTOK x 16)
// block: 512 threads, 16 tokens per block. W1 transposed into smem once.
// ---------------------------------------------------------------------------
__global__ __launch_bounds__(512) void kA(const float* __restrict__ hid,
                                          const float* __restrict__ W1)
{
    extern __shared__ float smA[];
    float* W1T = smA;               // [16][2052] padded rows
    float* xn  = smA + 16*2052;     // [2048]
    const int tid  = threadIdx.x;
    const int lane = tid & 31;
    const int wid  = tid >> 5;      // 16 warps == 16 r values

    for (int idx = tid; idx < MODEL*RANK; idx += 512) {
        W1T[(idx & 15)*2052 + (idx >> 4)] = W1[idx];
    }
    __syncthreads();

    const int tok0 = blockIdx.x * 16;
    for (int it = 0; it < 16; ++it) {
        const int tok = tok0 + it;
        // stage + normalize: thread loads 4 consecutive floats; warp == one head (128)
        float4 v = *(const float4*)(hid + (size_t)tok*MODEL + tid*4);
        float ss = v.x*v.x + v.y*v.y + v.z*v.z + v.w*v.w;
        #pragma unroll
        for (int o = 16; o > 0; o >>= 1) ss += __shfl_xor_sync(0xffffffffu, ss, o);
        const float inv = rsqrtf(ss + 1e-6f);
        float4 xv = make_float4(v.x*inv, v.y*inv, v.z*inv, v.w*inv);
        *(float4*)(xn + tid*4) = xv;
        __syncthreads();

        // GEMM: warp wid computes u_r, r = wid
        float acc = 0.f;
        const float* wrow = W1T + wid*2052;
        #pragma unroll
        for (int i = 0; i < 16; ++i) {
            const int d = lane*4 + i*128;
            float4 a  = *(const float4*)(xn   + d);
            float4 bb = *(const float4*)(wrow + d);
            acc += a.x*bb.x + a.y*bb.y + a.z*bb.z + a.w*bb.w;
        }
        #pragma unroll
        for (int o = 16; o > 0; o >>= 1) acc += __shfl_xor_sync(0xffffffffu, acc, o);
        if (lane == 0) g_u[tok*RANK + wid] = acc;
        __syncthreads();
    }
}

// ---------------------------------------------------------------------------
// Kernel B: inclusive cumsum over t (per b, per r). grid (16, 4), 1024 threads.
// ---------------------------------------------------------------------------
__global__ __launch_bounds__(1024) void kB()
{
    __shared__ float wsum[32];
    const int r = blockIdx.x, b = blockIdx.y;
    const int tid = threadIdx.x, lane = tid & 31, wid = tid >> 5;
    const float* up = g_u + ((size_t)b*SEQ_T)*RANK + r;
    const int t = tid*4;
    float u0 = up[(t+0)*RANK];
    float u1 = up[(t+1)*RANK];
    float u2 = up[(t+2)*RANK];
    float u3 = up[(t+3)*RANK];
    float v0 = u0, v1 = v0+u1, v2 = v1+u2, v3 = v2+u3;
    float s = v3;
    #pragma unroll
    for (int o = 1; o < 32; o <<= 1) { float n = __shfl_up_sync(0xffffffffu, s, o); if (lane >= o) s += n; }
    if (lane == 31) wsum[wid] = s;
    __syncthreads();
    if (wid == 0) {
        float ws = wsum[lane];
        #pragma unroll
        for (int o = 1; o < 32; o <<= 1) { float n = __shfl_up_sync(0xffffffffu, ws, o); if (lane >= o) ws += n; }
        wsum[lane] = ws;
    }
    __syncthreads();
    const float base = (wid > 0) ? wsum[wid-1] : 0.f;
    const float excl = base + s - v3;
    float* Up = g_U + ((size_t)b*SEQ_T)*RANK + r;
    Up[(t+0)*RANK] = excl + v0;
    Up[(t+1)*RANK] = excl + v1;
    Up[(t+2)*RANK] = excl + v2;
    Up[(t+3)*RANK] = excl + v3;
}

// ---------------------------------------------------------------------------
// Kernel C: PD = W2^T U (tiled in smem, reused by 4 conv taps), conv+temp ->
// angle, sincos, rotate q and k. 256 blocks x 64 tokens, 256 threads (4 d each)
// ---------------------------------------------------------------------------
__global__ __launch_bounds__(256, 2) void kC(const float* __restrict__ q,
                                             const float* __restrict__ k,
                                             const float* __restrict__ W2,
                                             const float* __restrict__ cw,
                                             float* __restrict__ out)
{
    extern __shared__ float smC[];
    float* PDs = smC;                // [11][1024]
    float* Us  = smC + 11*1024;      // [67][16]
    const int tid  = threadIdx.x;
    const int tok0 = blockIdx.x * 64;
    const int b    = tok0 >> 12;
    const int t0   = tok0 & 4095;

    for (int i = tid; i < 67*RANK; i += 256) {
        const int row = t0 - 3 + (i >> 4);
        Us[i] = (row < 0) ? 0.f : g_U[(((size_t)b << 12) + row)*RANK + (i & 15)];
    }

    const int d0 = tid << 2;
    const int hh = d0 >> 6;
    const size_t qoff0 = (size_t)(hh << 6) + d0;   // h*128 + j0
    const int j0 = d0 & 63;
    const float LNT = 0.20503692775998528f;        // ln(500000)/64
    const float4 tv = make_float4(expf(-LNT*(float)j0),
                                  expf(-LNT*(float)(j0+1)),
                                  expf(-LNT*(float)(j0+2)),
                                  expf(-LNT*(float)(j0+3)));
    float4 w2c[16];
    #pragma unroll
    for (int r = 0; r < 16; ++r) w2c[r] = *(const float4*)(W2 + r*DD + d0);
    float4 cvs[4];
    #pragma unroll
    for (int w = 0; w < 4; ++w) {
        float4 c = *(const float4*)(cw + w*DD + d0);
        cvs[w] = make_float4(c.x*tv.x, c.y*tv.y, c.z*tv.z, c.w*tv.w);
    }
    __syncthreads();

    for (int g = 0; g < 8; ++g) {
        // phase P: PD rows for tokens [g*8-3 .. g*8+7] (Us rows g*8 .. g*8+10)
        #pragma unroll
        for (int row = 0; row < 11; ++row) {
            const float* Ur = Us + (g*8 + row)*RANK;
            float4 a = make_float4(0.f, 0.f, 0.f, 0.f);
            #pragma unroll
            for (int r = 0; r < 16; ++r) {
                const float u = Ur[r];
                a.x = fmaf(w2c[r].x, u, a.x);
                a.y = fmaf(w2c[r].y, u, a.y);
                a.z = fmaf(w2c[r].z, u, a.z);
                a.w = fmaf(w2c[r].w, u, a.w);
            }
            *(float4*)(PDs + row*DD + d0) = a;
        }
        __syncthreads();

        // phase R: 8 tokens, conv over 4 PD rows -> angle -> sincos -> rotate
        for (int i = 0; i < 8; ++i) {
            const int tok = tok0 + g*8 + i;
            float4 p0 = *(const float4*)(PDs + (i    )*DD + d0);
            float4 p1 = *(const float4*)(PDs + (i + 1)*DD + d0);
            float4 p2 = *(const float4*)(PDs + (i + 2)*DD + d0);
            float4 p3 = *(const float4*)(PDs + (i + 3)*DD + d0);
            const float ax = cvs[0].x*p0.x + cvs[1].x*p1.x + cvs[2].x*p2.x + cvs[3].x*p3.x;
            const float ay = cvs[0].y*p0.y + cvs[1].y*p1.y + cvs[2].y*p2.y + cvs[3].y*p3.y;
            const float az = cvs[0].z*p0.z + cvs[1].z*p1.z + cvs[2].z*p2.z + cvs[3].z*p3.z;
            const float aw = cvs[0].w*p0.w + cvs[1].w*p1.w + cvs[2].w*p2.w + cvs[3].w*p3.w;
            float s0, c0, s1, c1, s2, c2, s3, c3;
            __sincosf(ax, &s0, &c0);
            __sincosf(ay, &s1, &c1);
            __sincosf(az, &s2, &c2);
            __sincosf(aw, &s3, &c3);

            const size_t base = (size_t)tok*2048 + qoff0;
            float4 q0 = *(const float4*)(q + base);
            float4 q1 = *(const float4*)(q + base + 64);
            float4 k0 = *(const float4*)(k + base);
            float4 k1 = *(const float4*)(k + base + 64);

            float4 o0, o1;
            o0.x = q0.x*c0 - q1.x*s0;  o1.x = q0.x*s0 + q1.x*c0;
            o0.y = q0.y*c1 - q1.y*s1;  o1.y = q0.y*s1 + q1.y*c1;
            o0.z = q0.z*c2 - q1.z*s2;  o1.z = q0.z*s2 + q1.z*c2;
            o0.w = q0.w*c3 - q1.w*s3;  o1.w = q0.w*s3 + q1.w*c3;
            *(float4*)(out + base)      = o0;
            *(float4*)(out + base + 64) = o1;

            o0.x = k0.x*c0 - k1.x*s0;  o1.x = k0.x*s0 + k1.x*c0;
            o0.y = k0.y*c1 - k1.y*s1;  o1.y = k0.y*s1 + k1.y*c1;
            o0.z = k0.z*c2 - k1.z*s2;  o1.z = k0.z*s2 + k1.z*c2;
            o0.w = k0.w*c3 - k1.w*s3;  o1.w = k0.w*s3 + k1.w*c3;
            *(float4*)(out + QK_ELEMS + base)      = o0;
            *(float4*)(out + QK_ELEMS + base + 64) = o1;
        }
        __syncthreads();
    }
}

// ---------------------------------------------------------------------------
extern "C" void kernel_launch(void* const* d_in, const int* in_sizes, int n_in,
                              void* d_out, int out_size)
{
    const float* q   = (const float*)d_in[0];
    const float* k   = (const float*)d_in[1];
    const float* hid = (const float*)d_in[2];
    const float* W1  = (const float*)d_in[3];
    const float* W2  = (const float*)d_in[4];
    const float* cw  = (const float*)d_in[5];
    float* out = (float*)d_out;

    const int SMEM_A = (16*2052 + 2048) * 4;         // 139520 B
    const int SMEM_C = (11*1024 + 67*16) * 4;        // 49344 B
    cudaFuncSetAttribute(kA, cudaFuncAttributeMaxDynamicSharedMemorySize, SMEM_A);
    cudaFuncSetAttribute(kC, cudaFuncAttributeMaxDynamicSharedMemorySize, SMEM_C);

    kA<<<NTOK/16, 512, SMEM_A>>>(hid, W1);
    kB<<<dim3(RANK, NUM_B), 1024>>>();
    kC<<<NTOK/64, 256, SMEM_C>>>(q, k, W2, cw, out);
}

// round 2
// speedup vs baseline: 1.9773x; 1.9773x over previous
#include <cuda_runtime.h>
#include <math.h>

#define NUM_B   4
#define SEQ_T   4096
#define NTOK    (NUM_B*SEQ_T)      // 16384
#define MODEL   2048
#define RANK    16
#define DD      1024               // NUM_HEADS * PE_DIM
#define QK_ELEMS 33554432          // NTOK*16*128

// scratch (allocation-free rule: __device__ globals)
__device__ float g_u[NTOK*RANK];   // x_norm @ W1
__device__ float g_U[NTOK*RANK];   // cumsum over t of g_u

// ---------------------------------------------------------------------------
// Kernel A (v2): warp-autonomous. Each warp processes 4 tokens:
//   per 128-wide head chunk: load x (4 LDG.128), shfl-reduce L2 norm,
//   stream W1^T rows from smem (conflict-free LDS.128) into 64 accumulators.
// No block-level serialization; FFMA-bound by design (~30us floor).
// ---------------------------------------------------------------------------
#define KA_BLOCKS 128
#define KA_WPB    16
__global__ __launch_bounds__(512) void kA(const float* __restrict__ hid,
                                          const float* __restrict__ W1)
{
    extern __shared__ float W1T[];   // [16][2052] padded rows (transposed W1)
    const int tid  = threadIdx.x;
    const int lane = tid & 31;
    const int wid  = tid >> 5;

    for (int idx = tid; idx < MODEL*RANK; idx += 512) {
        W1T[(idx & 15)*2052 + (idx >> 4)] = W1[idx];
    }
    __syncthreads();

    for (int task = blockIdx.x*KA_WPB + wid; task < NTOK/4; task += KA_BLOCKS*KA_WPB) {
        const int tok = task * 4;
        const float* xp = hid + (size_t)tok*MODEL + lane*4;

        float acc[4][16];
        #pragma unroll
        for (int t = 0; t < 4; ++t)
            #pragma unroll
            for (int r = 0; r < 16; ++r) acc[t][r] = 0.f;

        #pragma unroll
        for (int i = 0; i < 16; ++i) {          // head chunk (128 wide)
            float4 xv[4];
            #pragma unroll
            for (int t = 0; t < 4; ++t)
                xv[t] = *(const float4*)(xp + t*MODEL + i*128);

            // per-head L2 norm (4 tokens in flight)
            #pragma unroll
            for (int t = 0; t < 4; ++t) {
                float ss = xv[t].x*xv[t].x + xv[t].y*xv[t].y
                         + xv[t].z*xv[t].z + xv[t].w*xv[t].w;
                #pragma unroll
                for (int o = 16; o > 0; o >>= 1)
                    ss += __shfl_xor_sync(0xffffffffu, ss, o);
                const float inv = rsqrtf(ss + 1e-6f);
                xv[t].x *= inv; xv[t].y *= inv; xv[t].z *= inv; xv[t].w *= inv;
            }

            const float* wb = W1T + i*128 + lane*4;
            #pragma unroll
            for (int r = 0; r < 16; ++r) {
                float4 w = *(const float4*)(wb + r*2052);
                #pragma unroll
                for (int t = 0; t < 4; ++t) {
                    acc[t][r] = fmaf(xv[t].x, w.x,
                               fmaf(xv[t].y, w.y,
                               fmaf(xv[t].z, w.z,
                               fmaf(xv[t].w, w.w, acc[t][r]))));
                }
            }
        }

        // lane-reduce each of the 64 accumulators; lane r stores u[tok+t][r]
        #pragma unroll
        for (int t = 0; t < 4; ++t) {
            #pragma unroll
            for (int r = 0; r < 16; ++r) {
                float v = acc[t][r];
                #pragma unroll
                for (int o = 16; o > 0; o >>= 1)
                    v += __shfl_xor_sync(0xffffffffu, v, o);
                if (lane == r) g_u[(tok + t)*RANK + r] = v;
            }
        }
    }
}

// ---------------------------------------------------------------------------
// Kernel B: inclusive cumsum over t (per b, per r). grid (16, 4), 1024 threads.
// ---------------------------------------------------------------------------
__global__ __launch_bounds__(1024) void kB()
{
    __shared__ float wsum[32];
    const int r = blockIdx.x, b = blockIdx.y;
    const int tid = threadIdx.x, lane = tid & 31, wid = tid >> 5;
    const float* up = g_u + ((size_t)b*SEQ_T)*RANK + r;
    const int t = tid*4;
    float u0 = up[(t+0)*RANK];
    float u1 = up[(t+1)*RANK];
    float u2 = up[(t+2)*RANK];
    float u3 = up[(t+3)*RANK];
    float v0 = u0, v1 = v0+u1, v2 = v1+u2, v3 = v2+u3;
    float s = v3;
    #pragma unroll
    for (int o = 1; o < 32; o <<= 1) { float n = __shfl_up_sync(0xffffffffu, s, o); if (lane >= o) s += n; }
    if (lane == 31) wsum[wid] = s;
    __syncthreads();
    if (wid == 0) {
        float ws = wsum[lane];
        #pragma unroll
        for (int o = 1; o < 32; o <<= 1) { float n = __shfl_up_sync(0xffffffffu, ws, o); if (lane >= o) ws += n; }
        wsum[lane] = ws;
    }
    __syncthreads();
    const float base = (wid > 0) ? wsum[wid-1] : 0.f;
    const float excl = base + s - v3;
    float* Up = g_U + ((size_t)b*SEQ_T)*RANK + r;
    Up[(t+0)*RANK] = excl + v0;
    Up[(t+1)*RANK] = excl + v1;
    Up[(t+2)*RANK] = excl + v2;
    Up[(t+3)*RANK] = excl + v3;
}

// ---------------------------------------------------------------------------
// Kernel C: PD = W2^T U (tiled in smem, reused by 4 conv taps), conv+temp ->
// angle, sincos, rotate q and k. 256 blocks x 64 tokens, 256 threads (4 d each)
// ---------------------------------------------------------------------------
__global__ __launch_bounds__(256, 2) void kC(const float* __restrict__ q,
                                             const float* __restrict__ k,
                                             const float* __restrict__ W2,
                                             const float* __restrict__ cw,
                                             float* __restrict__ out)
{
    extern __shared__ float smC[];
    float* PDs = smC;                // [11][1024]
    float* Us  = smC + 11*1024;      // [67][16]
    const int tid  = threadIdx.x;
    const int tok0 = blockIdx.x * 64;
    const int b    = tok0 >> 12;
    const int t0   = tok0 & 4095;

    for (int i = tid; i < 67*RANK; i += 256) {
        const int row = t0 - 3 + (i >> 4);
        Us[i] = (row < 0) ? 0.f : g_U[(((size_t)b << 12) + row)*RANK + (i & 15)];
    }

    const int d0 = tid << 2;
    const int hh = d0 >> 6;
    const size_t qoff0 = (size_t)(hh << 6) + d0;   // h*128 + j0
    const int j0 = d0 & 63;
    const float LNT = 0.20503692775998528f;        // ln(500000)/64
    const float4 tv = make_float4(expf(-LNT*(float)j0),
                                  expf(-LNT*(float)(j0+1)),
                                  expf(-LNT*(float)(j0+2)),
                                  expf(-LNT*(float)(j0+3)));
    float4 w2c[16];
    #pragma unroll
    for (int r = 0; r < 16; ++r) w2c[r] = *(const float4*)(W2 + r*DD + d0);
    float4 cvs[4];
    #pragma unroll
    for (int w = 0; w < 4; ++w) {
        float4 c = *(const float4*)(cw + w*DD + d0);
        cvs[w] = make_float4(c.x*tv.x, c.y*tv.y, c.z*tv.z, c.w*tv.w);
    }
    __syncthreads();

    for (int g = 0; g < 8; ++g) {
        // phase P: PD rows for tokens [g*8-3 .. g*8+7] (Us rows g*8 .. g*8+10)
        #pragma unroll
        for (int row = 0; row < 11; ++row) {
            const float* Ur = Us + (g*8 + row)*RANK;
            float4 a = make_float4(0.f, 0.f, 0.f, 0.f);
            #pragma unroll
            for (int r = 0; r < 16; ++r) {
                const float u = Ur[r];
                a.x = fmaf(w2c[r].x, u, a.x);
                a.y = fmaf(w2c[r].y, u, a.y);
                a.z = fmaf(w2c[r].z, u, a.z);
                a.w = fmaf(w2c[r].w, u, a.w);
            }
            *(float4*)(PDs + row*DD + d0) = a;
        }
        __syncthreads();

        // phase R: 8 tokens, conv over 4 PD rows -> angle -> sincos -> rotate
        for (int i = 0; i < 8; ++i) {
            const int tok = tok0 + g*8 + i;
            float4 p0 = *(const float4*)(PDs + (i    )*DD + d0);
            float4 p1 = *(const float4*)(PDs + (i + 1)*DD + d0);
            float4 p2 = *(const float4*)(PDs + (i + 2)*DD + d0);
            float4 p3 = *(const float4*)(PDs + (i + 3)*DD + d0);
            const float ax = cvs[0].x*p0.x + cvs[1].x*p1.x + cvs[2].x*p2.x + cvs[3].x*p3.x;
            const float ay = cvs[0].y*p0.y + cvs[1].y*p1.y + cvs[2].y*p2.y + cvs[3].y*p3.y;
            const float az = cvs[0].z*p0.z + cvs[1].z*p1.z + cvs[2].z*p2.z + cvs[3].z*p3.z;
            const float aw = cvs[0].w*p0.w + cvs[1].w*p1.w + cvs[2].w*p2.w + cvs[3].w*p3.w;
            float s0, c0, s1, c1, s2, c2, s3, c3;
            __sincosf(ax, &s0, &c0);
            __sincosf(ay, &s1, &c1);
            __sincosf(az, &s2, &c2);
            __sincosf(aw, &s3, &c3);

            const size_t base = (size_t)tok*2048 + qoff0;
            float4 q0 = *(const float4*)(q + base);
            float4 q1 = *(const float4*)(q + base + 64);
            float4 k0 = *(const float4*)(k + base);
            float4 k1 = *(const float4*)(k + base + 64);

            float4 o0, o1;
            o0.x = q0.x*c0 - q1.x*s0;  o1.x = q0.x*s0 + q1.x*c0;
            o0.y = q0.y*c1 - q1.y*s1;  o1.y = q0.y*s1 + q1.y*c1;
            o0.z = q0.z*c2 - q1.z*s2;  o1.z = q0.z*s2 + q1.z*c2;
            o0.w = q0.w*c3 - q1.w*s3;  o1.w = q0.w*s3 + q1.w*c3;
            *(float4*)(out + base)      = o0;
            *(float4*)(out + base + 64) = o1;

            o0.x = k0.x*c0 - k1.x*s0;  o1.x = k0.x*s0 + k1.x*c0;
            o0.y = k0.y*c1 - k1.y*s1;  o1.y = k0.y*s1 + k1.y*c1;
            o0.z = k0.z*c2 - k1.z*s2;  o1.z = k0.z*s2 + k1.z*c2;
            o0.w = k0.w*c3 - k1.w*s3;  o1.w = k0.w*s3 + k1.w*c3;
            *(float4*)(out + QK_ELEMS + base)      = o0;
            *(float4*)(out + QK_ELEMS + base + 64) = o1;
        }
        __syncthreads();
    }
}

// ---------------------------------------------------------------------------
extern "C" void kernel_launch(void* const* d_in, const int* in_sizes, int n_in,
                              void* d_out, int out_size)
{
    const float* q   = (const float*)d_in[0];
    const float* k   = (const float*)d_in[1];
    const float* hid = (const float*)d_in[2];
    const float* W1  = (const float*)d_in[3];
    const float* W2  = (const float*)d_in[4];
    const float* cw  = (const float*)d_in[5];
    float* out = (float*)d_out;

    const int SMEM_A = (16*2052) * 4;                // 131328 B
    const int SMEM_C = (11*1024 + 67*16) * 4;        // 49344 B
    cudaFuncSetAttribute(kA, cudaFuncAttributeMaxDynamicSharedMemorySize, SMEM_A);
    cudaFuncSetAttribute(kC, cudaFuncAttributeMaxDynamicSharedMemorySize, SMEM_C);

    kA<<<KA_BLOCKS, 512, SMEM_A>>>(hid, W1);
    kB<<<dim3(RANK, NUM_B), 1024>>>();
    kC<<<NTOK/64, 256, SMEM_C>>>(q, k, W2, cw, out);
}

// round 4
// speedup vs baseline: 2.0514x; 1.0375x over previous
#include <cuda_runtime.h>
#include <math.h>

#define NUM_B   4
#define SEQ_T   4096
#define NTOK    (NUM_B*SEQ_T)      // 16384
#define MODEL   2048
#define RANK    16
#define DD      1024               // NUM_HEADS * PE_DIM
#define QK_ELEMS 33554432          // NTOK*16*128

// scratch (allocation-free rule: __device__ globals)
__device__ float g_u[NTOK*RANK];   // x_norm @ W1
__device__ float g_U[NTOK*RANK];   // cumsum over t of g_u

// ---- packed f32x2 helpers (sm_103a FFMA2 path, PTX-only) --------------------
__device__ __forceinline__ unsigned long long pk2(float a, float b) {
    unsigned long long r;
    asm("mov.b64 %0, {%1, %2};" : "=l"(r) : "f"(a), "f"(b));
    return r;
}
__device__ __forceinline__ void fma2(unsigned long long& d,
                                     unsigned long long a, unsigned long long b) {
    asm("fma.rn.f32x2 %0, %1, %2, %0;" : "+l"(d) : "l"(a), "l"(b));
}
__device__ __forceinline__ unsigned long long mul2(unsigned long long a,
                                                   unsigned long long b) {
    unsigned long long r;
    asm("mul.rn.f32x2 %0, %1, %2;" : "=l"(r) : "l"(a), "l"(b));
    return r;
}
__device__ __forceinline__ float foldadd2(unsigned long long v) {
    float a, b;
    asm("mov.b64 {%0, %1}, %2;" : "=f"(a), "=f"(b) : "l"(v));
    return a + b;
}

// ---------------------------------------------------------------------------
// Kernel A (v3): warp-pair r-split + packed FFMA2 + butterfly reduce.
//   Warp pair (p, half=0/1) shares the same 4 tokens; each half owns 8 of
//   the 16 r columns (halves W1 LDS traffic; x re-read hits L1).
//   Reduction dim packed as f32x2 (natural float4 pairs) -> FFMA count /2.
//   Output reduce: 31-shfl halving butterfly, lane l ends with output l.
// ---------------------------------------------------------------------------
#define KA_BLOCKS 128
__global__ __launch_bounds__(512) void kA(const float* __restrict__ hid,
                                          const float* __restrict__ W1)
{
    extern __shared__ float W1T[];   // [16][2052] padded rows (transposed W1)
    const int tid  = threadIdx.x;
    const int lane = tid & 31;
    const int wid  = tid >> 5;
    const int p    = wid & 7;        // pair id within block
    const int half = wid >> 3;       // which 8-r half this warp owns

    for (int idx = tid; idx < MODEL*RANK; idx += 512) {
        W1T[(idx & 15)*2052 + (idx >> 4)] = W1[idx];
    }
    __syncthreads();

    const float* wbase = W1T + half*8*2052 + lane*4;

    for (int task = blockIdx.x*8 + p; task < NTOK/4; task += KA_BLOCKS*8) {
        const int tok = task * 4;
        const float* xp = hid + (size_t)tok*MODEL + lane*4;

        unsigned long long acc[4][8];
        #pragma unroll
        for (int t = 0; t < 4; ++t)
            #pragma unroll
            for (int r = 0; r < 8; ++r) acc[t][r] = 0ull;

        float4 cur[4];
        #pragma unroll
        for (int t = 0; t < 4; ++t) cur[t] = *(const float4*)(xp + t*MODEL);

        #pragma unroll
        for (int i = 0; i < 16; ++i) {          // head chunk (128 wide)
            float4 nxt[4];
            #pragma unroll
            for (int t = 0; t < 4; ++t)
                nxt[t] = (i < 15) ? *(const float4*)(xp + t*MODEL + (i+1)*128)
                                  : make_float4(0.f, 0.f, 0.f, 0.f);

            // per-head L2 norm -> packed normalized x pairs
            unsigned long long xq0[4], xq1[4];
            #pragma unroll
            for (int t = 0; t < 4; ++t) {
                float ss = cur[t].x*cur[t].x + cur[t].y*cur[t].y
                         + cur[t].z*cur[t].z + cur[t].w*cur[t].w;
                #pragma unroll
                for (int o = 16; o > 0; o >>= 1)
                    ss += __shfl_xor_sync(0xffffffffu, ss, o);
                const float inv = rsqrtf(ss + 1e-6f);
                const unsigned long long iv = pk2(inv, inv);
                xq0[t] = mul2(pk2(cur[t].x, cur[t].y), iv);
                xq1[t] = mul2(pk2(cur[t].z, cur[t].w), iv);
            }

            const float* wb = wbase + i*128;
            #pragma unroll
            for (int r = 0; r < 8; ++r) {
                float4 w = *(const float4*)(wb + r*2052);
                const unsigned long long w0 = pk2(w.x, w.y);
                const unsigned long long w1 = pk2(w.z, w.w);
                #pragma unroll
                for (int t = 0; t < 4; ++t) {
                    fma2(acc[t][r], xq0[t], w0);
                    fma2(acc[t][r], xq1[t], w1);
                }
            }

            #pragma unroll
            for (int t = 0; t < 4; ++t) cur[t] = nxt[t];
        }

        // fold d-pairs, then 31-shfl halving butterfly across lanes.
        float v[32];
        #pragma unroll
        for (int t = 0; t < 4; ++t)
            #pragma unroll
            for (int r = 0; r < 8; ++r)
                v[t*8 + r] = foldadd2(acc[t][r]);

        #pragma unroll
        for (int o = 16; o >= 1; o >>= 1) {
            const bool up = (lane & o) != 0;
            #pragma unroll
            for (int j = 0; j < o; ++j) {
                float send = up ? v[j] : v[j + o];
                float keep = up ? v[j + o] : v[j];
                v[j] = keep + __shfl_xor_sync(0xffffffffu, send, o);
            }
        }
        // lane l holds the full sum for (t = l>>3, r = (l&7) + half*8)
        g_u[(tok + (lane >> 3))*RANK + (lane & 7) + half*8] = v[0];
    }
}

// ---------------------------------------------------------------------------
// Kernel B: inclusive cumsum over t (per b, per r). grid (16, 4), 1024 threads.
// ---------------------------------------------------------------------------
__global__ __launch_bounds__(1024) void kB()
{
    __shared__ float wsum[32];
    const int r = blockIdx.x, b = blockIdx.y;
    const int tid = threadIdx.x, lane = tid & 31, wid = tid >> 5;
    const float* up = g_u + ((size_t)b*SEQ_T)*RANK + r;
    const int t = tid*4;
    float u0 = up[(t+0)*RANK];
    float u1 = up[(t+1)*RANK];
    float u2 = up[(t+2)*RANK];
    float u3 = up[(t+3)*RANK];
    float v0 = u0, v1 = v0+u1, v2 = v1+u2, v3 = v2+u3;
    float s = v3;
    #pragma unroll
    for (int o = 1; o < 32; o <<= 1) { float n = __shfl_up_sync(0xffffffffu, s, o); if (lane >= o) s += n; }
    if (lane == 31) wsum[wid] = s;
    __syncthreads();
    if (wid == 0) {
        float ws = wsum[lane];
        #pragma unroll
        for (int o = 1; o < 32; o <<= 1) { float n = __shfl_up_sync(0xffffffffu, ws, o); if (lane >= o) ws += n; }
        wsum[lane] = ws;
    }
    __syncthreads();
    const float base = (wid > 0) ? wsum[wid-1] : 0.f;
    const float excl = base + s - v3;
    float* Up = g_U + ((size_t)b*SEQ_T)*RANK + r;
    Up[(t+0)*RANK] = excl + v0;
    Up[(t+1)*RANK] = excl + v1;
    Up[(t+2)*RANK] = excl + v2;
    Up[(t+3)*RANK] = excl + v3;
}

// ---------------------------------------------------------------------------
// Kernel C: PD = W2^T U (tiled in smem, reused by 4 conv taps), conv+temp ->
// angle, sincos, rotate q and k. 256 blocks x 64 tokens, 256 threads (4 d each)
// ---------------------------------------------------------------------------
__global__ __launch_bounds__(256, 2) void kC(const float* __restrict__ q,
                                             const float* __restrict__ k,
                                             const float* __restrict__ W2,
                                             const float* __restrict__ cw,
                                             float* __restrict__ out)
{
    extern __shared__ float smC[];
    float* PDs = smC;                // [11][1024]
    float* Us  = smC + 11*1024;      // [67][16]
    const int tid  = threadIdx.x;
    const int tok0 = blockIdx.x * 64;
    const int b    = tok0 >> 12;
    const int t0   = tok0 & 4095;

    for (int i = tid; i < 67*RANK; i += 256) {
        const int row = t0 - 3 + (i >> 4);
        Us[i] = (row < 0) ? 0.f : g_U[(((size_t)b << 12) + row)*RANK + (i & 15)];
    }

    const int d0 = tid << 2;
    const int hh = d0 >> 6;
    const size_t qoff0 = (size_t)(hh << 6) + d0;   // h*128 + j0
    const int j0 = d0 & 63;
    const float LNT = 0.20503692775998528f;        // ln(500000)/64
    const float4 tv = make_float4(expf(-LNT*(float)j0),
                                  expf(-LNT*(float)(j0+1)),
                                  expf(-LNT*(float)(j0+2)),
                                  expf(-LNT*(float)(j0+3)));
    float4 w2c[16];
    #pragma unroll
    for (int r = 0; r < 16; ++r) w2c[r] = *(const float4*)(W2 + r*DD + d0);
    float4 cvs[4];
    #pragma unroll
    for (int w = 0; w < 4; ++w) {
        float4 c = *(const float4*)(cw + w*DD + d0);
        cvs[w] = make_float4(c.x*tv.x, c.y*tv.y, c.z*tv.z, c.w*tv.w);
    }
    __syncthreads();

    for (int g = 0; g < 8; ++g) {
        // phase P: PD rows for tokens [g*8-3 .. g*8+7] (Us rows g*8 .. g*8+10)
        #pragma unroll
        for (int row = 0; row < 11; ++row) {
            const float* Ur = Us + (g*8 + row)*RANK;
            float4 a = make_float4(0.f, 0.f, 0.f, 0.f);
            #pragma unroll
            for (int r = 0; r < 16; ++r) {
                const float u = Ur[r];
                a.x = fmaf(w2c[r].x, u, a.x);
                a.y = fmaf(w2c[r].y, u, a.y);
                a.z = fmaf(w2c[r].z, u, a.z);
                a.w = fmaf(w2c[r].w, u, a.w);
            }
            *(float4*)(PDs + row*DD + d0) = a;
        }
        __syncthreads();

        // phase R: 8 tokens, conv over 4 PD rows -> angle -> sincos -> rotate
        for (int i = 0; i < 8; ++i) {
            const int tok = tok0 + g*8 + i;
            float4 p0 = *(const float4*)(PDs + (i    )*DD + d0);
            float4 p1 = *(const float4*)(PDs + (i + 1)*DD + d0);
            float4 p2 = *(const float4*)(PDs + (i + 2)*DD + d0);
            float4 p3 = *(const float4*)(PDs + (i + 3)*DD + d0);
            const float ax = cvs[0].x*p0.x + cvs[1].x*p1.x + cvs[2].x*p2.x + cvs[3].x*p3.x;
            const float ay = cvs[0].y*p0.y + cvs[1].y*p1.y + cvs[2].y*p2.y + cvs[3].y*p3.y;
            const float az = cvs[0].z*p0.z + cvs[1].z*p1.z + cvs[2].z*p2.z + cvs[3].z*p3.z;
            const float aw = cvs[0].w*p0.w + cvs[1].w*p1.w + cvs[2].w*p2.w + cvs[3].w*p3.w;
            float s0, c0, s1, c1, s2, c2, s3, c3;
            __sincosf(ax, &s0, &c0);
            __sincosf(ay, &s1, &c1);
            __sincosf(az, &s2, &c2);
            __sincosf(aw, &s3, &c3);

            const size_t base = (size_t)tok*2048 + qoff0;
            float4 q0 = *(const float4*)(q + base);
            float4 q1 = *(const float4*)(q + base + 64);
            float4 k0 = *(const float4*)(k + base);
            float4 k1 = *(const float4*)(k + base + 64);

            float4 o0, o1;
            o0.x = q0.x*c0 - q1.x*s0;  o1.x = q0.x*s0 + q1.x*c0;
            o0.y = q0.y*c1 - q1.y*s1;  o1.y = q0.y*s1 + q1.y*c1;
            o0.z = q0.z*c2 - q1.z*s2;  o1.z = q0.z*s2 + q1.z*c2;
            o0.w = q0.w*c3 - q1.w*s3;  o1.w = q0.w*s3 + q1.w*c3;
            *(float4*)(out + base)      = o0;
            *(float4*)(out + base + 64) = o1;

            o0.x = k0.x*c0 - k1.x*s0;  o1.x = k0.x*s0 + k1.x*c0;
            o0.y = k0.y*c1 - k1.y*s1;  o1.y = k0.y*s1 + k1.y*c1;
            o0.z = k0.z*c2 - k1.z*s2;  o1.z = k0.z*s2 + k1.z*c2;
            o0.w = k0.w*c3 - k1.w*s3;  o1.w = k0.w*s3 + k1.w*c3;
            *(float4*)(out + QK_ELEMS + base)      = o0;
            *(float4*)(out + QK_ELEMS + base + 64) = o1;
        }
        __syncthreads();
    }
}

// ---------------------------------------------------------------------------
extern "C" void kernel_launch(void* const* d_in, const int* in_sizes, int n_in,
                              void* d_out, int out_size)
{
    const float* q   = (const float*)d_in[0];
    const float* k   = (const float*)d_in[1];
    const float* hid = (const float*)d_in[2];
    const float* W1  = (const float*)d_in[3];
    const float* W2  = (const float*)d_in[4];
    const float* cw  = (const float*)d_in[5];
    float* out = (float*)d_out;

    const int SMEM_A = (16*2052) * 4;                // 131328 B
    const int SMEM_C = (11*1024 + 67*16) * 4;        // 49344 B
    cudaFuncSetAttribute(kA, cudaFuncAttributeMaxDynamicSharedMemorySize, SMEM_A);
    cudaFuncSetAttribute(kC, cudaFuncAttributeMaxDynamicSharedMemorySize, SMEM_C);

    kA<<<KA_BLOCKS, 512, SMEM_A>>>(hid, W1);
    kB<<<dim3(RANK, NUM_B), 1024>>>();
    kC<<<NTOK/64, 256, SMEM_C>>>(q, k, W2, cw, out);
}

// round 6
// speedup vs baseline: 2.1537x; 1.0499x over previous
#include <cuda_runtime.h>
#include <math.h>
#include <stdint.h>

#define NUM_B   4
#define SEQ_T   4096
#define NTOK    (NUM_B*SEQ_T)      // 16384
#define MODEL   2048
#define RANK    16
#define DD      1024               // NUM_HEADS * PE_DIM
#define QK_ELEMS 33554432          // NTOK*16*128

// scratch (allocation-free rule: __device__ globals)
__device__ float g_u[NTOK*RANK];   // x_norm @ W1
__device__ float g_U[NTOK*RANK];   // cumsum over t of g_u

// ---- packed f32x2 helpers (sm_103a FFMA2 path, PTX-only) --------------------
__device__ __forceinline__ unsigned long long pk2(float a, float b) {
    unsigned long long r;
    asm("mov.b64 %0, {%1, %2};" : "=l"(r) : "f"(a), "f"(b));
    return r;
}
__device__ __forceinline__ void fma2(unsigned long long& d,
                                     unsigned long long a, unsigned long long b) {
    asm("fma.rn.f32x2 %0, %1, %2, %0;" : "+l"(d) : "l"(a), "l"(b));
}
__device__ __forceinline__ unsigned long long mul2(unsigned long long a,
                                                   unsigned long long b) {
    unsigned long long r;
    asm("mul.rn.f32x2 %0, %1, %2;" : "=l"(r) : "l"(a), "l"(b));
    return r;
}
__device__ __forceinline__ float foldadd2(unsigned long long v) {
    float a, b;
    asm("mov.b64 {%0, %1}, %2;" : "=f"(a), "=f"(b) : "l"(v));
    return a + b;
}
__device__ __forceinline__ void cp16(uint32_t dst, const void* src) {
    asm volatile("cp.async.cg.shared.global [%0], [%1], 16;"
                 :: "r"(dst), "l"(src) : "memory");
}
__device__ __forceinline__ void cp_commit() {
    asm volatile("cp.async.commit_group;" ::: "memory");
}
__device__ __forceinline__ void cp_wait2() {
    asm volatile("cp.async.wait_group 2;" ::: "memory");
}

// ---------------------------------------------------------------------------
// Kernel A (v5): warp-pair r-split + FFMA2 + depth-3 cp.async smem ring.
//   Pair (p) shares 4 tokens; warp half=0/1 owns 8 of 16 r-columns AND
//   stages 2 of the 4 tokens via cp.async.cg (16B) into a 4-slot ring.
//   x is read from DRAM exactly once (no duplicate LDG), consumed via LDS.
//   One named barrier per chunk orders partner staging vs compute.
// ---------------------------------------------------------------------------
#define KA_BLOCKS 128
__global__ __launch_bounds__(512) void kA(const float* __restrict__ hid,
                                          const float* __restrict__ W1)
{
    extern __shared__ float smA[];
    float* W1T = smA;                      // [16][2052] transposed W1
    float* Xb  = smA + 16*2052;            // [8 pairs][4 slots][4 tok][128]
    const int tid  = threadIdx.x;
    const int lane = tid & 31;
    const int wid  = tid >> 5;
    const int p    = wid & 7;              // pair id
    const int half = wid >> 3;             // r-half / token-half owner

    for (int idx = tid; idx < MODEL*RANK; idx += 512) {
        W1T[(idx & 15)*2052 + (idx >> 4)] = W1[idx];
    }
    __syncthreads();

    const float* wbase = W1T + half*8*2052 + lane*4;
    float* Xp = Xb + p*(4*4*128);          // this pair's ring (2048 floats)
    const uint32_t xp_s = (uint32_t)__cvta_generic_to_shared(Xp);
    const int barid = p + 1;

    for (int task = blockIdx.x*8 + p; task < NTOK/4; task += KA_BLOCKS*8) {
        const int tok = task * 4;
        const float* xg = hid + (size_t)tok*MODEL + lane*4;

        // stage chunk c: this warp copies tokens half*2, half*2+1
        #define KA_STAGE(c)                                                    \
            {   const int _c = (c);                                            \
                _Pragma("unroll")                                              \
                for (int j = 0; j < 2; ++j) {                                  \
                    const int t = half*2 + j;                                  \
                    cp16(xp_s + (((_c & 3)*512 + t*128 + lane*4) << 2),        \
                         xg + (size_t)t*MODEL + _c*128);                       \
                }                                                              \
            }

        KA_STAGE(0); cp_commit();
        KA_STAGE(1); cp_commit();
        KA_STAGE(2); cp_commit();

        unsigned long long acc[4][8];
        #pragma unroll
        for (int t = 0; t < 4; ++t)
            #pragma unroll
            for (int r = 0; r < 8; ++r) acc[t][r] = 0ull;

        #pragma unroll
        for (int c = 0; c < 16; ++c) {
            cp_wait2();                                  // chunk c resident (own half)
            asm volatile("bar.sync %0, 64;" :: "r"(barid) : "memory");  // partner half too

            const float* xs = Xp + (c & 3)*512 + lane*4;
            float4 xv[4];
            #pragma unroll
            for (int t = 0; t < 4; ++t) xv[t] = *(const float4*)(xs + t*128);

            // per-head L2 norm -> packed normalized x pairs
            unsigned long long xq0[4], xq1[4];
            #pragma unroll
            for (int t = 0; t < 4; ++t) {
                float ss = xv[t].x*xv[t].x + xv[t].y*xv[t].y
                         + xv[t].z*xv[t].z + xv[t].w*xv[t].w;
                #pragma unroll
                for (int o = 16; o > 0; o >>= 1)
                    ss += __shfl_xor_sync(0xffffffffu, ss, o);
                const float inv = rsqrtf(ss + 1e-6f);
                const unsigned long long iv = pk2(inv, inv);
                xq0[t] = mul2(pk2(xv[t].x, xv[t].y), iv);
                xq1[t] = mul2(pk2(xv[t].z, xv[t].w), iv);
            }

            const float* wb = wbase + c*128;
            #pragma unroll
            for (int r = 0; r < 8; ++r) {
                float4 w = *(const float4*)(wb + r*2052);
                const unsigned long long w0 = pk2(w.x, w.y);
                const unsigned long long w1 = pk2(w.z, w.w);
                #pragma unroll
                for (int t = 0; t < 4; ++t) {
                    fma2(acc[t][r], xq0[t], w0);
                    fma2(acc[t][r], xq1[t], w1);
                }
            }

            if (c + 3 < 16) { KA_STAGE(c + 3); }
            cp_commit();                                 // uniform 1 group / iter
        }
        #undef KA_STAGE

        // fold d-pairs, then 31-shfl halving butterfly across lanes.
        float v[32];
        #pragma unroll
        for (int t = 0; t < 4; ++t)
            #pragma unroll
            for (int r = 0; r < 8; ++r)
                v[t*8 + r] = foldadd2(acc[t][r]);

        #pragma unroll
        for (int o = 16; o >= 1; o >>= 1) {
            const bool up = (lane & o) != 0;
            #pragma unroll
            for (int j = 0; j < o; ++j) {
                float send = up ? v[j] : v[j + o];
                float keep = up ? v[j + o] : v[j];
                v[j] = keep + __shfl_xor_sync(0xffffffffu, send, o);
            }
        }
        // lane l holds the full sum for (t = l>>3, r = (l&7) + half*8)
        g_u[(tok + (lane >> 3))*RANK + (lane & 7) + half*8] = v[0];
    }
}

// ---------------------------------------------------------------------------
// Kernel B: inclusive cumsum over t (per b, per r). grid (16, 4), 1024 threads.
// ---------------------------------------------------------------------------
__global__ __launch_bounds__(1024) void kB()
{
    __shared__ float wsum[32];
    const int r = blockIdx.x, b = blockIdx.y;
    const int tid = threadIdx.x, lane = tid & 31, wid = tid >> 5;
    const float* up = g_u + ((size_t)b*SEQ_T)*RANK + r;
    const int t = tid*4;
    float u0 = up[(t+0)*RANK];
    float u1 = up[(t+1)*RANK];
    float u2 = up[(t+2)*RANK];
    float u3 = up[(t+3)*RANK];
    float v0 = u0, v1 = v0+u1, v2 = v1+u2, v3 = v2+u3;
    float s = v3;
    #pragma unroll
    for (int o = 1; o < 32; o <<= 1) { float n = __shfl_up_sync(0xffffffffu, s, o); if (lane >= o) s += n; }
    if (lane == 31) wsum[wid] = s;
    __syncthreads();
    if (wid == 0) {
        float ws = wsum[lane];
        #pragma unroll
        for (int o = 1; o < 32; o <<= 1) { float n = __shfl_up_sync(0xffffffffu, ws, o); if (lane >= o) ws += n; }
        wsum[lane] = ws;
    }
    __syncthreads();
    const float base = (wid > 0) ? wsum[wid-1] : 0.f;
    const float excl = base + s - v3;
    float* Up = g_U + ((size_t)b*SEQ_T)*RANK + r;
    Up[(t+0)*RANK] = excl + v0;
    Up[(t+1)*RANK] = excl + v1;
    Up[(t+2)*RANK] = excl + v2;
    Up[(t+3)*RANK] = excl + v3;
}

// ---------------------------------------------------------------------------
// Kernel C: PD = W2^T U (tiled in smem, reused by 4 conv taps), conv+temp ->
// angle, sincos, rotate q and k. 256 blocks x 64 tokens, 256 threads (4 d each)
// ---------------------------------------------------------------------------
__global__ __launch_bounds__(256, 2) void kC(const float* __restrict__ q,
                                             const float* __restrict__ k,
                                             const float* __restrict__ W2,
                                             const float* __restrict__ cw,
                                             float* __restrict__ out)
{
    extern __shared__ float smC[];
    float* PDs = smC;                // [11][1024]
    float* Us  = smC + 11*1024;      // [67][16]
    const int tid  = threadIdx.x;
    const int tok0 = blockIdx.x * 64;
    const int b    = tok0 >> 12;
    const int t0   = tok0 & 4095;

    for (int i = tid; i < 67*RANK; i += 256) {
        const int row = t0 - 3 + (i >> 4);
        Us[i] = (row < 0) ? 0.f : g_U[(((size_t)b << 12) + row)*RANK + (i & 15)];
    }

    const int d0 = tid << 2;
    const int hh = d0 >> 6;
    const size_t qoff0 = (size_t)(hh << 6) + d0;   // h*128 + j0
    const int j0 = d0 & 63;
    const float LNT = 0.20503692775998528f;        // ln(500000)/64
    const float4 tv = make_float4(expf(-LNT*(float)j0),
                                  expf(-LNT*(float)(j0+1)),
                                  expf(-LNT*(float)(j0+2)),
                                  expf(-LNT*(float)(j0+3)));
    float4 w2c[16];
    #pragma unroll
    for (int r = 0; r < 16; ++r) w2c[r] = *(const float4*)(W2 + r*DD + d0);
    float4 cvs[4];
    #pragma unroll
    for (int w = 0; w < 4; ++w) {
        float4 c = *(const float4*)(cw + w*DD + d0);
        cvs[w] = make_float4(c.x*tv.x, c.y*tv.y, c.z*tv.z, c.w*tv.w);
    }
    __syncthreads();

    for (int g = 0; g < 8; ++g) {
        // phase P: PD rows for tokens [g*8-3 .. g*8+7] (Us rows g*8 .. g*8+10)
        #pragma unroll
        for (int row = 0; row < 11; ++row) {
            const float* Ur = Us + (g*8 + row)*RANK;
            float4 a = make_float4(0.f, 0.f, 0.f, 0.f);
            #pragma unroll
            for (int r = 0; r < 16; ++r) {
                const float u = Ur[r];
                a.x = fmaf(w2c[r].x, u, a.x);
                a.y = fmaf(w2c[r].y, u, a.y);
                a.z = fmaf(w2c[r].z, u, a.z);
                a.w = fmaf(w2c[r].w, u, a.w);
            }
            *(float4*)(PDs + row*DD + d0) = a;
        }
        __syncthreads();

        // phase R: 8 tokens, conv over 4 PD rows -> angle -> sincos -> rotate
        for (int i = 0; i < 8; ++i) {
            const int tok = tok0 + g*8 + i;
            float4 p0 = *(const float4*)(PDs + (i    )*DD + d0);
            float4 p1 = *(const float4*)(PDs + (i + 1)*DD + d0);
            float4 p2 = *(const float4*)(PDs + (i + 2)*DD + d0);
            float4 p3 = *(const float4*)(PDs + (i + 3)*DD + d0);
            const float ax = cvs[0].x*p0.x + cvs[1].x*p1.x + cvs[2].x*p2.x + cvs[3].x*p3.x;
            const float ay = cvs[0].y*p0.y + cvs[1].y*p1.y + cvs[2].y*p2.y + cvs[3].y*p3.y;
            const float az = cvs[0].z*p0.z + cvs[1].z*p1.z + cvs[2].z*p2.z + cvs[3].z*p3.z;
            const float aw = cvs[0].w*p0.w + cvs[1].w*p1.w + cvs[2].w*p2.w + cvs[3].w*p3.w;
            float s0, c0, s1, c1, s2, c2, s3, c3;
            __sincosf(ax, &s0, &c0);
            __sincosf(ay, &s1, &c1);
            __sincosf(az, &s2, &c2);
            __sincosf(aw, &s3, &c3);

            const size_t base = (size_t)tok*2048 + qoff0;
            float4 q0 = *(const float4*)(q + base);
            float4 q1 = *(const float4*)(q + base + 64);
            float4 k0 = *(const float4*)(k + base);
            float4 k1 = *(const float4*)(k + base + 64);

            float4 o0, o1;
            o0.x = q0.x*c0 - q1.x*s0;  o1.x = q0.x*s0 + q1.x*c0;
            o0.y = q0.y*c1 - q1.y*s1;  o1.y = q0.y*s1 + q1.y*c1;
            o0.z = q0.z*c2 - q1.z*s2;  o1.z = q0.z*s2 + q1.z*c2;
            o0.w = q0.w*c3 - q1.w*s3;  o1.w = q0.w*s3 + q1.w*c3;
            *(float4*)(out + base)      = o0;
            *(float4*)(out + base + 64) = o1;

            o0.x = k0.x*c0 - k1.x*s0;  o1.x = k0.x*s0 + k1.x*c0;
            o0.y = k0.y*c1 - k1.y*s1;  o1.y = k0.y*s1 + k1.y*c1;
            o0.z = k0.z*c2 - k1.z*s2;  o1.z = k0.z*s2 + k1.z*c2;
            o0.w = k0.w*c3 - k1.w*s3;  o1.w = k0.w*s3 + k1.w*c3;
            *(float4*)(out + QK_ELEMS + base)      = o0;
            *(float4*)(out + QK_ELEMS + base + 64) = o1;
        }
        __syncthreads();
    }
}

// ---------------------------------------------------------------------------
extern "C" void kernel_launch(void* const* d_in, const int* in_sizes, int n_in,
                              void* d_out, int out_size)
{
    const float* q   = (const float*)d_in[0];
    const float* k   = (const float*)d_in[1];
    const float* hid = (const float*)d_in[2];
    const float* W1  = (const float*)d_in[3];
    const float* W2  = (const float*)d_in[4];
    const float* cw  = (const float*)d_in[5];
    float* out = (float*)d_out;

    const int SMEM_A = (16*2052 + 8*4*4*128) * 4;    // 131328 + 65536 = 196864 B
    const int SMEM_C = (11*1024 + 67*16) * 4;        // 49344 B
    cudaFuncSetAttribute(kA, cudaFuncAttributeMaxDynamicSharedMemorySize, SMEM_A);
    cudaFuncSetAttribute(kC, cudaFuncAttributeMaxDynamicSharedMemorySize, SMEM_C);

    kA<<<KA_BLOCKS, 512, SMEM_A>>>(hid, W1);
    kB<<<dim3(RANK, NUM_B), 1024>>>();
    kC<<<NTOK/64, 256, SMEM_C>>>(q, k, W2, cw, out);
}

// round 7
// speedup vs baseline: 2.2983x; 1.0671x over previous
#include <cuda_runtime.h>
#include <math.h>
#include <stdint.h>

#define NUM_B   4
#define SEQ_T   4096
#define NTOK    (NUM_B*SEQ_T)      // 16384
#define MODEL   2048
#define RANK    16
#define DD      1024               // NUM_HEADS * PE_DIM
#define QK_ELEMS 33554432          // NTOK*16*128

typedef unsigned long long ull;

// scratch (allocation-free rule: __device__ globals)
__device__ float g_u[NTOK*RANK];   // x_norm @ W1
__device__ float g_U[NTOK*RANK];   // cumsum over t of g_u

// ---- packed f32x2 helpers (sm_103a FFMA2 path, PTX-only) --------------------
__device__ __forceinline__ ull pk2(float a, float b) {
    ull r;
    asm("mov.b64 %0, {%1, %2};" : "=l"(r) : "f"(a), "f"(b));
    return r;
}
__device__ __forceinline__ void fma2(ull& d, ull a, ull b) {
    asm("fma.rn.f32x2 %0, %1, %2, %0;" : "+l"(d) : "l"(a), "l"(b));
}
__device__ __forceinline__ ull add2(ull a, ull b) {
    ull r;
    asm("add.rn.f32x2 %0, %1, %2;" : "=l"(r) : "l"(a), "l"(b));
    return r;
}
__device__ __forceinline__ float fcomp(float4 v, int i) {
    switch (i) { case 0: return v.x; case 1: return v.y; case 2: return v.z; default: return v.w; }
}

// ---------------------------------------------------------------------------
// Kernel A (v6): fully warp-autonomous. Each warp: 4 tokens, all 16 r.
//   FFMA2 packed over r-PAIRS (native W1 layout has r adjacent).
//   W1 in smem plane layout [(c*4+dd)*8+rp][lane] (ull, conflict-free LDS.64).
//   x: direct LDG.128, depth-2 register prefetch. No cross-warp sync at all.
//   Output: 31x 64-bit butterfly with packed add, one 8B STG per lane.
// ---------------------------------------------------------------------------
#define KA_BLOCKS 128
__global__ __launch_bounds__(512) void kA(const float* __restrict__ hid,
                                          const float* __restrict__ W1)
{
    extern __shared__ float Wsm[];   // 32768 floats = 131072 B
    const int tid  = threadIdx.x;
    const int lane = tid & 31;
    const int wid  = tid >> 5;

    // stage W1 into plane layout: word addr = ((c*4+dd)*8 + rp)*64 + l*2 + hi
    // where d = c*128 + l*4 + dd, r = 2*rp + hi   (native W1[d*16 + r])
    for (int idx = tid; idx < MODEL*RANK; idx += 512) {
        const int d = idx >> 4, r = idx & 15;
        const int c = d >> 7, l = (d >> 2) & 31, dd = d & 3;
        Wsm[((((c << 2) + dd) << 3) + (r >> 1))*64 + l*2 + (r & 1)] = W1[idx];
    }
    __syncthreads();

    const ull* Wsu = (const ull*)Wsm;

    for (int task = blockIdx.x*16 + wid; task < NTOK/4; task += KA_BLOCKS*16) {
        const int tok = task * 4;
        const float* xg = hid + (size_t)tok*MODEL + lane*4;

        float4 xq[2][4];
        #pragma unroll
        for (int pf = 0; pf < 2; ++pf)
            #pragma unroll
            for (int t = 0; t < 4; ++t)
                xq[pf][t] = *(const float4*)(xg + (size_t)t*MODEL + pf*128);

        ull acc[4][8];
        #pragma unroll
        for (int t = 0; t < 4; ++t)
            #pragma unroll
            for (int r = 0; r < 8; ++r) acc[t][r] = 0ull;

        #pragma unroll
        for (int c = 0; c < 16; ++c) {
            const int buf = c & 1;

            // per-head L2 norm (head == 128-wide chunk)
            float ss[4];
            #pragma unroll
            for (int t = 0; t < 4; ++t) {
                float4 v = xq[buf][t];
                ss[t] = v.x*v.x + v.y*v.y + v.z*v.z + v.w*v.w;
            }
            #pragma unroll
            for (int o = 16; o > 0; o >>= 1) {
                #pragma unroll
                for (int t = 0; t < 4; ++t)
                    ss[t] += __shfl_xor_sync(0xffffffffu, ss[t], o);
            }
            float inv[4];
            #pragma unroll
            for (int t = 0; t < 4; ++t) inv[t] = rsqrtf(ss[t] + 1e-6f);

            // FFMA2 over r-pairs
            const ull* wc = Wsu + c*1024 + lane;   // c-plane: 4 dd x 8 rp x 32 ull
            #pragma unroll
            for (int dd = 0; dd < 4; ++dd) {
                ull xpt[4];
                #pragma unroll
                for (int t = 0; t < 4; ++t) {
                    const float xs = fcomp(xq[buf][t], dd) * inv[t];
                    xpt[t] = pk2(xs, xs);
                }
                const ull* wp = wc + dd*256;
                #pragma unroll
                for (int rp = 0; rp < 8; ++rp) {
                    const ull w = wp[rp*32];
                    #pragma unroll
                    for (int t = 0; t < 4; ++t)
                        fma2(acc[t][rp], xpt[t], w);
                }
            }

            // prefetch chunk c+2 into the buffer just consumed
            if (c < 14) {
                #pragma unroll
                for (int t = 0; t < 4; ++t)
                    xq[buf][t] = *(const float4*)(xg + (size_t)t*MODEL + (c+2)*128);
            }
        }

        // 31x 64-bit halving butterfly; lane l ends with (t = l>>3, rp = l&7)
        ull v[32];
        #pragma unroll
        for (int t = 0; t < 4; ++t)
            #pragma unroll
            for (int rp = 0; rp < 8; ++rp)
                v[t*8 + rp] = acc[t][rp];

        #pragma unroll
        for (int o = 16; o >= 1; o >>= 1) {
            const bool up = (lane & o) != 0;
            #pragma unroll
            for (int j = 0; j < o; ++j) {
                ull send = up ? v[j] : v[j + o];
                ull keep = up ? v[j + o] : v[j];
                v[j] = add2(keep, __shfl_xor_sync(0xffffffffu, send, o));
            }
        }
        *(ull*)(g_u + (tok + (lane >> 3))*RANK + (lane & 7)*2) = v[0];
    }
}

// ---------------------------------------------------------------------------
// Kernel B: inclusive cumsum over t (per b, per r). grid (16, 4), 1024 threads.
// ---------------------------------------------------------------------------
__global__ __launch_bounds__(1024) void kB()
{
    __shared__ float wsum[32];
    const int r = blockIdx.x, b = blockIdx.y;
    const int tid = threadIdx.x, lane = tid & 31, wid = tid >> 5;
    const float* up = g_u + ((size_t)b*SEQ_T)*RANK + r;
    const int t = tid*4;
    float u0 = up[(t+0)*RANK];
    float u1 = up[(t+1)*RANK];
    float u2 = up[(t+2)*RANK];
    float u3 = up[(t+3)*RANK];
    float v0 = u0, v1 = v0+u1, v2 = v1+u2, v3 = v2+u3;
    float s = v3;
    #pragma unroll
    for (int o = 1; o < 32; o <<= 1) { float n = __shfl_up_sync(0xffffffffu, s, o); if (lane >= o) s += n; }
    if (lane == 31) wsum[wid] = s;
    __syncthreads();
    if (wid == 0) {
        float ws = wsum[lane];
        #pragma unroll
        for (int o = 1; o < 32; o <<= 1) { float n = __shfl_up_sync(0xffffffffu, ws, o); if (lane >= o) ws += n; }
        wsum[lane] = ws;
    }
    __syncthreads();
    const float base = (wid > 0) ? wsum[wid-1] : 0.f;
    const float excl = base + s - v3;
    float* Up = g_U + ((size_t)b*SEQ_T)*RANK + r;
    Up[(t+0)*RANK] = excl + v0;
    Up[(t+1)*RANK] = excl + v1;
    Up[(t+2)*RANK] = excl + v2;
    Up[(t+3)*RANK] = excl + v3;
}

// ---------------------------------------------------------------------------
// Kernel C: PD = W2^T U (tiled in smem, reused by 4 conv taps), conv+temp ->
// angle, sincos, rotate q and k. 256 blocks x 64 tokens, 256 threads (4 d each)
// ---------------------------------------------------------------------------
__global__ __launch_bounds__(256, 2) void kC(const float* __restrict__ q,
                                             const float* __restrict__ k,
                                             const float* __restrict__ W2,
                                             const float* __restrict__ cw,
                                             float* __restrict__ out)
{
    extern __shared__ float smC[];
    float* PDs = smC;                // [11][1024]
    float* Us  = smC + 11*1024;      // [67][16]
    const int tid  = threadIdx.x;
    const int tok0 = blockIdx.x * 64;
    const int b    = tok0 >> 12;
    const int t0   = tok0 & 4095;

    for (int i = tid; i < 67*RANK; i += 256) {
        const int row = t0 - 3 + (i >> 4);
        Us[i] = (row < 0) ? 0.f : g_U[(((size_t)b << 12) + row)*RANK + (i & 15)];
    }

    const int d0 = tid << 2;
    const int hh = d0 >> 6;
    const size_t qoff0 = (size_t)(hh << 6) + d0;   // h*128 + j0
    const int j0 = d0 & 63;
    const float LNT = 0.20503692775998528f;        // ln(500000)/64
    const float4 tv = make_float4(expf(-LNT*(float)j0),
                                  expf(-LNT*(float)(j0+1)),
                                  expf(-LNT*(float)(j0+2)),
                                  expf(-LNT*(float)(j0+3)));
    float4 w2c[16];
    #pragma unroll
    for (int r = 0; r < 16; ++r) w2c[r] = *(const float4*)(W2 + r*DD + d0);
    float4 cvs[4];
    #pragma unroll
    for (int w = 0; w < 4; ++w) {
        float4 c = *(const float4*)(cw + w*DD + d0);
        cvs[w] = make_float4(c.x*tv.x, c.y*tv.y, c.z*tv.z, c.w*tv.w);
    }
    __syncthreads();

    for (int g = 0; g < 8; ++g) {
        // phase P: PD rows for tokens [g*8-3 .. g*8+7] (Us rows g*8 .. g*8+10)
        #pragma unroll
        for (int row = 0; row < 11; ++row) {
            const float* Ur = Us + (g*8 + row)*RANK;
            float4 a = make_float4(0.f, 0.f, 0.f, 0.f);
            #pragma unroll
            for (int r = 0; r < 16; ++r) {
                const float u = Ur[r];
                a.x = fmaf(w2c[r].x, u, a.x);
                a.y = fmaf(w2c[r].y, u, a.y);
                a.z = fmaf(w2c[r].z, u, a.z);
                a.w = fmaf(w2c[r].w, u, a.w);
            }
            *(float4*)(PDs + row*DD + d0) = a;
        }
        __syncthreads();

        // phase R: 8 tokens, conv over 4 PD rows -> angle -> sincos -> rotate
        for (int i = 0; i < 8; ++i) {
            const int tok = tok0 + g*8 + i;
            float4 p0 = *(const float4*)(PDs + (i    )*DD + d0);
            float4 p1 = *(const float4*)(PDs + (i + 1)*DD + d0);
            float4 p2 = *(const float4*)(PDs + (i + 2)*DD + d0);
            float4 p3 = *(const float4*)(PDs + (i + 3)*DD + d0);
            const float ax = cvs[0].x*p0.x + cvs[1].x*p1.x + cvs[2].x*p2.x + cvs[3].x*p3.x;
            const float ay = cvs[0].y*p0.y + cvs[1].y*p1.y + cvs[2].y*p2.y + cvs[3].y*p3.y;
            const float az = cvs[0].z*p0.z + cvs[1].z*p1.z + cvs[2].z*p2.z + cvs[3].z*p3.z;
            const float aw = cvs[0].w*p0.w + cvs[1].w*p1.w + cvs[2].w*p2.w + cvs[3].w*p3.w;
            float s0, c0, s1, c1, s2, c2, s3, c3;
            __sincosf(ax, &s0, &c0);
            __sincosf(ay, &s1, &c1);
            __sincosf(az, &s2, &c2);
            __sincosf(aw, &s3, &c3);

            const size_t base = (size_t)tok*2048 + qoff0;
            float4 q0 = *(const float4*)(q + base);
            float4 q1 = *(const float4*)(q + base + 64);
            float4 k0 = *(const float4*)(k + base);
            float4 k1 = *(const float4*)(k + base + 64);

            float4 o0, o1;
            o0.x = q0.x*c0 - q1.x*s0;  o1.x = q0.x*s0 + q1.x*c0;
            o0.y = q0.y*c1 - q1.y*s1;  o1.y = q0.y*s1 + q1.y*c1;
            o0.z = q0.z*c2 - q1.z*s2;  o1.z = q0.z*s2 + q1.z*c2;
            o0.w = q0.w*c3 - q1.w*s3;  o1.w = q0.w*s3 + q1.w*c3;
            *(float4*)(out + base)      = o0;
            *(float4*)(out + base + 64) = o1;

            o0.x = k0.x*c0 - k1.x*s0;  o1.x = k0.x*s0 + k1.x*c0;
            o0.y = k0.y*c1 - k1.y*s1;  o1.y = k0.y*s1 + k1.y*c1;
            o0.z = k0.z*c2 - k1.z*s2;  o1.z = k0.z*s2 + k1.z*c2;
            o0.w = k0.w*c3 - k1.w*s3;  o1.w = k0.w*s3 + k1.w*c3;
            *(float4*)(out + QK_ELEMS + base)      = o0;
            *(float4*)(out + QK_ELEMS + base + 64) = o1;
        }
        __syncthreads();
    }
}

// ---------------------------------------------------------------------------
extern "C" void kernel_launch(void* const* d_in, const int* in_sizes, int n_in,
                              void* d_out, int out_size)
{
    const float* q   = (const float*)d_in[0];
    const float* k   = (const float*)d_in[1];
    const float* hid = (const float*)d_in[2];
    const float* W1  = (const float*)d_in[3];
    const float* W2  = (const float*)d_in[4];
    const float* cw  = (const float*)d_in[5];
    float* out = (float*)d_out;

    const int SMEM_A = MODEL*RANK*4;                 // 131072 B
    const int SMEM_C = (11*1024 + 67*16) * 4;        // 49344 B
    cudaFuncSetAttribute(kA, cudaFuncAttributeMaxDynamicSharedMemorySize, SMEM_A);
    cudaFuncSetAttribute(kC, cudaFuncAttributeMaxDynamicSharedMemorySize, SMEM_C);

    kA<<<KA_BLOCKS, 512, SMEM_A>>>(hid, W1);
    kB<<<dim3(RANK, NUM_B), 1024>>>();
    kC<<<NTOK/64, 256, SMEM_C>>>(q, k, W2, cw, out);
}